// round 15
// baseline (speedup 1.0000x reference)
#include <cuda_runtime.h>
#include <cuda_fp16.h>
#include <stdint.h>
#include <cstdint>
#include <math.h>

#define B_  2
#define S_  2048
#define D_  1024
#define H_  16
#define DH_ 64
#define E_  16
#define F_  256
#define T_  (B_*S_)

// ---------------- scratch ----------------
__device__ __half g_wqkvT[(size_t)3*D_*D_];   // transposed [N][K] per matrix
__device__ __half g_woT[(size_t)D_*D_];
__device__ __half g_w1T[(size_t)E_*F_*D_];    // per-expert [F][D]
__device__ __half g_w2T[(size_t)E_*D_*F_];    // per-expert [D][F]
__device__ __half g_h1h[(size_t)T_*D_];
__device__ __half g_qkvh[(size_t)3*T_*D_];
__device__ __half g_ctxh[(size_t)T_*D_];
__device__ __half g_h2h[(size_t)T_*D_];
__device__ __half g_uph[(size_t)E_*T_*F_];
__device__ float g_h2[(size_t)T_*D_];
__device__ int   g_cnt[E_];
__device__ int   g_elist[E_*T_];
__device__ float g_egate[E_*T_];

__global__ void zero_cnt_kernel() {
    if (threadIdx.x < E_) g_cnt[threadIdx.x] = 0;
}

// ---------------- helpers ----------------
__device__ __forceinline__ unsigned packh(float lo, float hi) {
    unsigned u;
    asm("cvt.rn.f16x2.f32 %0, %1, %2;" : "=r"(u) : "f"(hi), "f"(lo));
    return u;
}

__device__ __forceinline__ void mma16(float* d, const unsigned* a, unsigned b0, unsigned b1) {
    asm volatile(
        "mma.sync.aligned.m16n8k16.row.col.f32.f16.f16.f32 "
        "{%0,%1,%2,%3},{%4,%5,%6,%7},{%8,%9},{%0,%1,%2,%3};"
        : "+f"(d[0]), "+f"(d[1]), "+f"(d[2]), "+f"(d[3])
        : "r"(a[0]), "r"(a[1]), "r"(a[2]), "r"(a[3]), "r"(b0), "r"(b1));
}

__device__ __forceinline__ uint32_t smem_u32(const void* p) {
    uint32_t a;
    asm("{ .reg .u64 t; cvta.to.shared.u64 t, %1; cvt.u32.u64 %0, t; }" : "=r"(a) : "l"(p));
    return a;
}

__device__ __forceinline__ void ldsm4(unsigned* r, uint32_t addr) {
    asm volatile("ldmatrix.sync.aligned.m8n8.x4.shared.b16 {%0,%1,%2,%3}, [%4];"
                 : "=r"(r[0]), "=r"(r[1]), "=r"(r[2]), "=r"(r[3]) : "r"(addr));
}

__device__ __forceinline__ void ldsm4t(unsigned* r, uint32_t addr) {
    asm volatile("ldmatrix.sync.aligned.m8n8.x4.trans.shared.b16 {%0,%1,%2,%3}, [%4];"
                 : "=r"(r[0]), "=r"(r[1]), "=r"(r[2]), "=r"(r[3]) : "r"(addr));
}

#define CP_ASYNC16(dst, src) \
    asm volatile("cp.async.cg.shared.global [%0], [%1], 16;" :: "r"(dst), "l"(src))
#define CP_COMMIT() asm volatile("cp.async.commit_group;")
#define CP_WAIT(n)  asm volatile("cp.async.wait_group %0;" :: "n"(n))

// ---------------- fp32 [1024][1024] -> transposed fp16 [N][K] -------------------
__global__ __launch_bounds__(256) void conv_f2h_T(const float* __restrict__ s,
                                                  __half* __restrict__ d) {
    __shared__ float t[32][33];
    int bx = blockIdx.x * 32;
    int by = blockIdx.y * 32;
    int lx = threadIdx.x & 31, ly = threadIdx.x >> 5;
#pragma unroll
    for (int i = 0; i < 4; i++) {
        int r = ly + i * 8;
        t[r][lx] = s[(size_t)(by + r) * 1024 + bx + lx];
    }
    __syncthreads();
#pragma unroll
    for (int i = 0; i < 4; i++) {
        int r = ly + i * 8;
        d[(size_t)(bx + r) * 1024 + by + lx] = __float2half(t[lx][r]);
    }
}

// ---------------- fused QKV transpose (z selects matrix) -----------------------
__global__ __launch_bounds__(256) void conv_f2h_T3(const float* __restrict__ s0,
                                                   const float* __restrict__ s1,
                                                   const float* __restrict__ s2,
                                                   __half* __restrict__ d) {
    const float* s = (blockIdx.z == 0) ? s0 : ((blockIdx.z == 1) ? s1 : s2);
    __half* dz = d + (size_t)blockIdx.z * 1024 * 1024;
    __shared__ float t[32][33];
    int bx = blockIdx.x * 32;
    int by = blockIdx.y * 32;
    int lx = threadIdx.x & 31, ly = threadIdx.x >> 5;
#pragma unroll
    for (int i = 0; i < 4; i++) {
        int r = ly + i * 8;
        t[r][lx] = s[(size_t)(by + r) * 1024 + bx + lx];
    }
    __syncthreads();
#pragma unroll
    for (int i = 0; i < 4; i++) {
        int r = ly + i * 8;
        dz[(size_t)(bx + r) * 1024 + by + lx] = __float2half(t[lx][r]);
    }
}

// ---------------- per-expert fp32 [R][C] -> fp16 [C][R] ------------------------
__global__ __launch_bounds__(256) void conv_TE(const float* __restrict__ s,
                                               __half* __restrict__ d,
                                               int R, int C) {
    const float* se = s + (size_t)blockIdx.z * R * C;
    __half* de = d + (size_t)blockIdx.z * R * C;
    __shared__ float t[32][33];
    int bx = blockIdx.x * 32;
    int by = blockIdx.y * 32;
    int lx = threadIdx.x & 31, ly = threadIdx.x >> 5;
#pragma unroll
    for (int i = 0; i < 4; i++) {
        int r = ly + i * 8;
        t[r][lx] = se[(size_t)(by + r) * C + bx + lx];
    }
    __syncthreads();
#pragma unroll
    for (int i = 0; i < 4; i++) {
        int r = ly + i * 8;
        de[(size_t)(bx + r) * R + by + lx] = __float2half(t[lx][r]);
    }
}

// ---------------- LayerNorm (fp16 out) ----------------
__global__ __launch_bounds__(256) void ln_h_kernel(const float* __restrict__ x,
                                                   const float* __restrict__ sc,
                                                   const float* __restrict__ bi,
                                                   __half* __restrict__ o) {
    int t = blockIdx.x;
    const float* xr = x + (size_t)t * D_;
    __half* orow = o + (size_t)t * D_;
    float v[4];
    float s = 0.f, s2 = 0.f;
#pragma unroll
    for (int i = 0; i < 4; i++) {
        v[i] = xr[threadIdx.x + i * 256];
        s  += v[i];
        s2 += v[i] * v[i];
    }
#pragma unroll
    for (int off = 16; off; off >>= 1) {
        s  += __shfl_xor_sync(0xffffffffu, s,  off);
        s2 += __shfl_xor_sync(0xffffffffu, s2, off);
    }
    __shared__ float ws[8], ws2[8];
    int w = threadIdx.x >> 5, ln = threadIdx.x & 31;
    if (ln == 0) { ws[w] = s; ws2[w] = s2; }
    __syncthreads();
    float S = 0.f, S2 = 0.f;
#pragma unroll
    for (int i = 0; i < 8; i++) { S += ws[i]; S2 += ws2[i]; }
    float mu  = S * (1.0f / D_);
    float var = S2 * (1.0f / D_) - mu * mu;
    float inv = rsqrtf(var + 1e-5f);
#pragma unroll
    for (int i = 0; i < 4; i++) {
        int d = threadIdx.x + i * 256;
        orow[d] = __float2half((v[i] - mu) * inv * sc[d] + bi[d]);
    }
}

// ---------------- LayerNorm dual output (fp32 + fp16) ----------------
__global__ __launch_bounds__(256) void ln_dual_kernel(const float* __restrict__ x,
                                                      const float* __restrict__ sc,
                                                      const float* __restrict__ bi,
                                                      float* __restrict__ of,
                                                      __half* __restrict__ oh) {
    int t = blockIdx.x;
    const float* xr = x + (size_t)t * D_;
    float v[4];
    float s = 0.f, s2 = 0.f;
#pragma unroll
    for (int i = 0; i < 4; i++) {
        v[i] = xr[threadIdx.x + i * 256];
        s  += v[i];
        s2 += v[i] * v[i];
    }
#pragma unroll
    for (int off = 16; off; off >>= 1) {
        s  += __shfl_xor_sync(0xffffffffu, s,  off);
        s2 += __shfl_xor_sync(0xffffffffu, s2, off);
    }
    __shared__ float ws[8], ws2[8];
    int w = threadIdx.x >> 5, ln = threadIdx.x & 31;
    if (ln == 0) { ws[w] = s; ws2[w] = s2; }
    __syncthreads();
    float S = 0.f, S2 = 0.f;
#pragma unroll
    for (int i = 0; i < 8; i++) { S += ws[i]; S2 += ws2[i]; }
    float mu  = S * (1.0f / D_);
    float var = S2 * (1.0f / D_) - mu * mu;
    float inv = rsqrtf(var + 1e-5f);
#pragma unroll
    for (int i = 0; i < 4; i++) {
        int d = threadIdx.x + i * 256;
        float r = (v[i] - mu) * inv * sc[d] + bi[d];
        of[(size_t)t * D_ + d] = r;
        oh[(size_t)t * D_ + d] = __float2half(r);
    }
}

// ---------------- GEMM: ldmatrix + cp.async 3-stage, occ-2 ----------------------
#define STG_ 36864
#define TCSM (3 * STG_)

template <int MODE>
__global__ __launch_bounds__(256, 2) void gemm_ld(const __half* __restrict__ A,
                                                  const __half* __restrict__ Bt,
                                                  const float* __restrict__ Res,
                                                  float* __restrict__ Cf,
                                                  __half* __restrict__ Cb) {
    extern __shared__ char dsm[];
    uint32_t smb = smem_u32(dsm);

    int tid = threadIdx.x, warp = tid >> 5, lane = tid & 31;
    int g = lane >> 2, t4 = lane & 3;
    int wm = warp >> 1, wn = warp & 1;
    int bx = blockIdx.x * 128, by = blockIdx.y * 128;
    const __half* Bz = Bt + (size_t)blockIdx.z * D_ * D_;

    float acc[2][8][4];
#pragma unroll
    for (int i = 0; i < 2; i++)
#pragma unroll
        for (int j = 0; j < 8; j++)
#pragma unroll
            for (int q = 0; q < 4; q++) acc[i][j][q] = 0.f;

    int lr = tid >> 1;
    int lsh = (tid & 1) * 32;
    int lsb = (tid & 1) * 64;
    const __half* gA = A  + (size_t)(by + lr) * D_ + lsh;
    const __half* gB = Bz + (size_t)(bx + lr) * D_ + lsh;
    uint32_t sA = smb + lr * 144 + lsb;
    uint32_t sB = smb + 18432 + lr * 144 + lsb;

#pragma unroll
    for (int j = 0; j < 4; j++) {
        CP_ASYNC16(sA + j * 16, gA + j * 8);
        CP_ASYNC16(sB + j * 16, gB + j * 8);
    }
    CP_COMMIT();
#pragma unroll
    for (int j = 0; j < 4; j++) {
        CP_ASYNC16(sA + STG_ + j * 16, gA + 64 + j * 8);
        CP_ASYNC16(sB + STG_ + j * 16, gB + 64 + j * 8);
    }
    CP_COMMIT();

    uint32_t a_off = (uint32_t)((wm * 32 + (lane & 15)) * 144 + (lane >> 4) * 16);
    uint32_t b_row = (uint32_t)(wn * 64 + ((lane >> 4) & 1) * 8 + (lane & 7));
    uint32_t b_khb = ((lane >> 3) & 1) * 16;

    for (int i = 0; i < 16; i++) {
        int s = i % 3;
        if (i < 15) { CP_WAIT(1); } else { CP_WAIT(0); }
        __syncthreads();
        if (i + 2 < 16) {
            int s2 = (i + 2) % 3;
            int k0 = (i + 2) * 64;
#pragma unroll
            for (int j = 0; j < 4; j++) {
                CP_ASYNC16(sA + s2 * STG_ + j * 16, gA + k0 + j * 8);
                CP_ASYNC16(sB + s2 * STG_ + j * 16, gB + k0 + j * 8);
            }
            CP_COMMIT();
        }

        uint32_t ab = smb + s * STG_;
        uint32_t bb = ab + 18432;
#pragma unroll
        for (int kc = 0; kc < 4; kc++) {
            unsigned afr0[4], afr1[4];
            ldsm4(afr0, ab + a_off + kc * 32);
            ldsm4(afr1, ab + a_off + 16 * 144 + kc * 32);
#pragma unroll
            for (int p = 0; p < 4; p++) {
                unsigned bfr[4];
                ldsm4(bfr, bb + (b_row + p * 16) * 144 + b_khb + kc * 32);
                mma16(acc[0][2 * p],     afr0, bfr[0], bfr[1]);
                mma16(acc[0][2 * p + 1], afr0, bfr[2], bfr[3]);
                mma16(acc[1][2 * p],     afr1, bfr[0], bfr[1]);
                mma16(acc[1][2 * p + 1], afr1, bfr[2], bfr[3]);
            }
        }
    }

    if (MODE == 0) {
        __half* Cz = Cb + (size_t)blockIdx.z * T_ * D_;
#pragma unroll
        for (int mt = 0; mt < 2; mt++) {
#pragma unroll
            for (int nt = 0; nt < 8; nt++) {
                int col = bx + wn * 64 + nt * 8 + 2 * t4;
                size_t r0 = (size_t)(by + wm * 32 + mt * 16 + g);
                *(unsigned*)(Cz + r0 * D_ + col)       = packh(acc[mt][nt][0], acc[mt][nt][1]);
                *(unsigned*)(Cz + (r0 + 8) * D_ + col) = packh(acc[mt][nt][2], acc[mt][nt][3]);
            }
        }
    } else {
#pragma unroll
        for (int mt = 0; mt < 2; mt++) {
#pragma unroll
            for (int nt = 0; nt < 8; nt++) {
                int col = bx + wn * 64 + nt * 8 + 2 * t4;
                size_t r0 = (size_t)(by + wm * 32 + mt * 16 + g);
                size_t r1 = r0 + 8;
                float2 v01 = {acc[mt][nt][0], acc[mt][nt][1]};
                float2 v23 = {acc[mt][nt][2], acc[mt][nt][3]};
                float2 q0 = *(const float2*)(Res + r0 * D_ + col);
                float2 q1 = *(const float2*)(Res + r1 * D_ + col);
                v01.x += q0.x; v01.y += q0.y;
                v23.x += q1.x; v23.y += q1.y;
                *(float2*)(Cf + r0 * D_ + col) = v01;
                *(float2*)(Cf + r1 * D_ + col) = v23;
            }
        }
    }
}

// ---------------- MoE GEMM: ldmatrix + cp.async, gather/scatter, occ-2 ----------
template <int MODE>
__global__ __launch_bounds__(256, 2) void moe_ld(const __half* __restrict__ Ab,
                                                 const __half* __restrict__ Wt,
                                                 __half* __restrict__ Uph,
                                                 float* __restrict__ out) {
    const int Nn = (MODE == 0) ? F_ : D_;
    const int Kk = (MODE == 0) ? D_ : F_;
    const int NT = Kk / 64;
    int e = blockIdx.z;
    int n = g_cnt[e];
    int rb = blockIdx.y * 128;
    if (rb >= n) return;

    extern __shared__ char dsm[];
    uint32_t smb = smem_u32(dsm);

    int tid = threadIdx.x, warp = tid >> 5, lane = tid & 31;
    int g = lane >> 2, t4 = lane & 3;
    int wm = warp >> 1, wn = warp & 1;
    int bx = blockIdx.x * 128;
    const __half* Wz = Wt + (size_t)e * Kk * Nn;

    float acc[2][8][4];
#pragma unroll
    for (int i = 0; i < 2; i++)
#pragma unroll
        for (int j = 0; j < 8; j++)
#pragma unroll
            for (int q = 0; q < 4; q++) acc[i][j][q] = 0.f;

    int lr = tid >> 1;
    int lsh = (tid & 1) * 32;
    int lsb = (tid & 1) * 64;
    const __half* gA;
    if (MODE == 0) {
        int rg = rb + lr;
        int row = (rg < n) ? g_elist[e * T_ + rg] : 0;
        gA = Ab + (size_t)row * D_ + lsh;
    } else {
        gA = Ab + ((size_t)e * T_ + rb + lr) * F_ + lsh;
    }
    const __half* gB = Wz + (size_t)(bx + lr) * Kk + lsh;
    uint32_t sA = smb + lr * 144 + lsb;
    uint32_t sB = smb + 18432 + lr * 144 + lsb;

#pragma unroll
    for (int j = 0; j < 4; j++) {
        CP_ASYNC16(sA + j * 16, gA + j * 8);
        CP_ASYNC16(sB + j * 16, gB + j * 8);
    }
    CP_COMMIT();
#pragma unroll
    for (int j = 0; j < 4; j++) {
        CP_ASYNC16(sA + STG_ + j * 16, gA + 64 + j * 8);
        CP_ASYNC16(sB + STG_ + j * 16, gB + 64 + j * 8);
    }
    CP_COMMIT();

    uint32_t a_off = (uint32_t)((wm * 32 + (lane & 15)) * 144 + (lane >> 4) * 16);
    uint32_t b_row = (uint32_t)(wn * 64 + ((lane >> 4) & 1) * 8 + (lane & 7));
    uint32_t b_khb = ((lane >> 3) & 1) * 16;

    for (int i = 0; i < NT; i++) {
        int s = i % 3;
        if (i < NT - 1) { CP_WAIT(1); } else { CP_WAIT(0); }
        __syncthreads();
        if (i + 2 < NT) {
            int s2 = (i + 2) % 3;
            int k0 = (i + 2) * 64;
#pragma unroll
            for (int j = 0; j < 4; j++) {
                CP_ASYNC16(sA + s2 * STG_ + j * 16, gA + k0 + j * 8);
                CP_ASYNC16(sB + s2 * STG_ + j * 16, gB + k0 + j * 8);
            }
            CP_COMMIT();
        }

        uint32_t ab = smb + s * STG_;
        uint32_t bb = ab + 18432;
#pragma unroll
        for (int kc = 0; kc < 4; kc++) {
            unsigned afr0[4], afr1[4];
            ldsm4(afr0, ab + a_off + kc * 32);
            ldsm4(afr1, ab + a_off + 16 * 144 + kc * 32);
#pragma unroll
            for (int p = 0; p < 4; p++) {
                unsigned bfr[4];
                ldsm4(bfr, bb + (b_row + p * 16) * 144 + b_khb + kc * 32);
                mma16(acc[0][2 * p],     afr0, bfr[0], bfr[1]);
                mma16(acc[0][2 * p + 1], afr0, bfr[2], bfr[3]);
                mma16(acc[1][2 * p],     afr1, bfr[0], bfr[1]);
                mma16(acc[1][2 * p + 1], afr1, bfr[2], bfr[3]);
            }
        }
    }

    if (MODE == 0) {
#pragma unroll
        for (int mt = 0; mt < 2; mt++) {
            int rg0 = rb + wm * 32 + mt * 16 + g;
            int rg1 = rg0 + 8;
            float gt0 = (rg0 < n) ? g_egate[e * T_ + rg0] : 0.f;
            float gt1 = (rg1 < n) ? g_egate[e * T_ + rg1] : 0.f;
#pragma unroll
            for (int nt = 0; nt < 8; nt++) {
                int col = bx + wn * 64 + nt * 8 + 2 * t4;
                if (rg0 < n)
                    *(unsigned*)(Uph + ((size_t)e * T_ + rg0) * F_ + col) =
                        packh(fmaxf(acc[mt][nt][0], 0.f) * gt0,
                              fmaxf(acc[mt][nt][1], 0.f) * gt0);
                if (rg1 < n)
                    *(unsigned*)(Uph + ((size_t)e * T_ + rg1) * F_ + col) =
                        packh(fmaxf(acc[mt][nt][2], 0.f) * gt1,
                              fmaxf(acc[mt][nt][3], 0.f) * gt1);
            }
        }
    } else {
#pragma unroll
        for (int mt = 0; mt < 2; mt++) {
            int rg0 = rb + wm * 32 + mt * 16 + g;
            int rg1 = rg0 + 8;
            int t0 = (rg0 < n) ? g_elist[e * T_ + rg0] : -1;
            int t1 = (rg1 < n) ? g_elist[e * T_ + rg1] : -1;
#pragma unroll
            for (int nt = 0; nt < 8; nt++) {
                int col = bx + wn * 64 + nt * 8 + 2 * t4;
                if (t0 >= 0) {
                    atomicAdd(out + (size_t)t0 * D_ + col,     acc[mt][nt][0]);
                    atomicAdd(out + (size_t)t0 * D_ + col + 1, acc[mt][nt][1]);
                }
                if (t1 >= 0) {
                    atomicAdd(out + (size_t)t1 * D_ + col,     acc[mt][nt][2]);
                    atomicAdd(out + (size_t)t1 * D_ + col + 1, acc[mt][nt][3]);
                }
            }
        }
    }
}

// ---------------- fp16 flash attention: 128-q tile, cp.async 3-stage KV, occ-2 --
// Stage layout: 128 rows x 144 B (rows 0-63 = K, rows 64-127 = V).
#define AST_ 18432
#define ATSM (3 * AST_)

__global__ __launch_bounds__(256, 2) void attn_h_kernel(const __half* __restrict__ Q,
                                                        const __half* __restrict__ Kb,
                                                        const __half* __restrict__ Vb,
                                                        __half* __restrict__ O) {
    extern __shared__ char dsm[];
    uint32_t smb = smem_u32(dsm);
    unsigned* KVs = (unsigned*)dsm;

    int bh = blockIdx.y;
    int b = bh >> 4, h = bh & 15;
    int q0 = blockIdx.x * 128;
    int tid = threadIdx.x, warp = tid >> 5, lane = tid & 31;
    int g = lane >> 2, t4 = lane & 3;

    // ---- stage Q tile (128 rows) into stage 0, read fragments ----
#pragma unroll
    for (int i = 0; i < 4; i++) {
        int idx = tid + i * 256;
        int row = idx >> 3, uq = idx & 7;
        *(uint4*)&KVs[row * 36 + uq * 4] =
            *(const uint4*)(Q + (size_t)(b * S_ + q0 + row) * D_ + h * 64 + uq * 8);
    }
    __syncthreads();
    unsigned qf[4][4];
    {
        uint32_t qa = smb + (warp * 16 + (lane & 15)) * 144 + (lane >> 4) * 16;
#pragma unroll
        for (int kc = 0; kc < 4; kc++) ldsm4(qf[kc], qa + kc * 32);
    }
    __syncthreads();   // qf reads complete before stage 0 is overwritten

    // ---- cp.async loader setup: 64B per thread, rows 0-63 K, 64-127 V ----
    int lr = tid >> 1;
    int lsh = (tid & 1) * 32;
    int lsb = (tid & 1) * 64;
    const __half* gKV = (lr < 64)
        ? (Kb + (size_t)(b * S_ + lr) * D_ + h * 64 + lsh)
        : (Vb + (size_t)(b * S_ + lr - 64) * D_ + h * 64 + lsh);
    uint32_t sKV = smb + lr * 144 + lsb;

    // prologue: tiles 0 and 1
#pragma unroll
    for (int j = 0; j < 4; j++) CP_ASYNC16(sKV + j * 16, gKV + j * 8);
    CP_COMMIT();
#pragma unroll
    for (int j = 0; j < 4; j++) CP_ASYNC16(sKV + AST_ + j * 16, gKV + (size_t)64 * D_ + j * 8);
    CP_COMMIT();

    float oacc[8][4];
#pragma unroll
    for (int i = 0; i < 8; i++)
#pragma unroll
        for (int j = 0; j < 4; j++) oacc[i][j] = 0.f;
    float m0 = -1e30f, m1 = -1e30f, l0 = 0.f, l1 = 0.f;

    uint32_t k_row = ((lane >> 4) & 1) * 8 + (lane & 7);
    uint32_t k_khb = ((lane >> 3) & 1) * 16;
    uint32_t v_tok = ((lane >> 3) & 1) * 8 + (lane & 7);
    uint32_t v_dcb = ((lane >> 4) & 1) * 16;

    const int NT = S_ / 64;   // 32
    for (int i = 0; i < NT; i++) {
        int s = i % 3;
        if (i < NT - 1) { CP_WAIT(1); } else { CP_WAIT(0); }
        __syncthreads();
        if (i + 2 < NT) {
            int s2 = (i + 2) % 3;
            size_t go = (size_t)(i + 2) * 64 * D_;
#pragma unroll
            for (int j = 0; j < 4; j++) CP_ASYNC16(sKV + s2 * AST_ + j * 16, gKV + go + j * 8);
            CP_COMMIT();
        }

        uint32_t kbase = smb + s * AST_;
        uint32_t vbase = kbase + 64 * 144;

        // ---- S = Q @ K^T ----
        float sacc[8][4];
#pragma unroll
        for (int ii = 0; ii < 8; ii++)
#pragma unroll
            for (int j = 0; j < 4; j++) sacc[ii][j] = 0.f;
#pragma unroll
        for (int kc = 0; kc < 4; kc++) {
#pragma unroll
            for (int p = 0; p < 4; p++) {
                unsigned kb[4];
                ldsm4(kb, kbase + (k_row + p * 16) * 144 + k_khb + kc * 32);
                mma16(sacc[2 * p],     qf[kc], kb[0], kb[1]);
                mma16(sacc[2 * p + 1], qf[kc], kb[2], kb[3]);
            }
        }
#pragma unroll
        for (int nt = 0; nt < 8; nt++)
#pragma unroll
            for (int j = 0; j < 4; j++) sacc[nt][j] *= 0.125f;

        // ---- online softmax ----
        float mx0 = -1e30f, mx1 = -1e30f;
#pragma unroll
        for (int nt = 0; nt < 8; nt++) {
            mx0 = fmaxf(mx0, fmaxf(sacc[nt][0], sacc[nt][1]));
            mx1 = fmaxf(mx1, fmaxf(sacc[nt][2], sacc[nt][3]));
        }
        mx0 = fmaxf(mx0, __shfl_xor_sync(0xffffffffu, mx0, 1));
        mx0 = fmaxf(mx0, __shfl_xor_sync(0xffffffffu, mx0, 2));
        mx1 = fmaxf(mx1, __shfl_xor_sync(0xffffffffu, mx1, 1));
        mx1 = fmaxf(mx1, __shfl_xor_sync(0xffffffffu, mx1, 2));
        float mn0 = fmaxf(m0, mx0), mn1 = fmaxf(m1, mx1);
        float al0 = __expf(m0 - mn0), al1 = __expf(m1 - mn1);
        float rs0 = 0.f, rs1 = 0.f;
#pragma unroll
        for (int nt = 0; nt < 8; nt++) {
            sacc[nt][0] = __expf(sacc[nt][0] - mn0);
            sacc[nt][1] = __expf(sacc[nt][1] - mn0);
            sacc[nt][2] = __expf(sacc[nt][2] - mn1);
            sacc[nt][3] = __expf(sacc[nt][3] - mn1);
            rs0 += sacc[nt][0] + sacc[nt][1];
            rs1 += sacc[nt][2] + sacc[nt][3];
        }
        rs0 += __shfl_xor_sync(0xffffffffu, rs0, 1);
        rs0 += __shfl_xor_sync(0xffffffffu, rs0, 2);
        rs1 += __shfl_xor_sync(0xffffffffu, rs1, 1);
        rs1 += __shfl_xor_sync(0xffffffffu, rs1, 2);
        l0 = l0 * al0 + rs0;
        l1 = l1 * al1 + rs1;
        m0 = mn0; m1 = mn1;
#pragma unroll
        for (int dt = 0; dt < 8; dt++) {
            oacc[dt][0] *= al0; oacc[dt][1] *= al0;
            oacc[dt][2] *= al1; oacc[dt][3] *= al1;
        }

        // ---- O += P @ V ----
#pragma unroll
        for (int kc = 0; kc < 4; kc++) {
            unsigned pf[4];
            pf[0] = packh(sacc[2 * kc][0],     sacc[2 * kc][1]);
            pf[1] = packh(sacc[2 * kc][2],     sacc[2 * kc][3]);
            pf[2] = packh(sacc[2 * kc + 1][0], sacc[2 * kc + 1][1]);
            pf[3] = packh(sacc[2 * kc + 1][2], sacc[2 * kc + 1][3]);
#pragma unroll
            for (int p = 0; p < 4; p++) {
                unsigned vb[4];
                ldsm4t(vb, vbase + (v_tok + kc * 16) * 144 + v_dcb + p * 32);
                mma16(oacc[2 * p],     pf, vb[0], vb[1]);
                mma16(oacc[2 * p + 1], pf, vb[2], vb[3]);
            }
        }
    }

    float il0 = 1.0f / l0, il1 = 1.0f / l1;
    int row = q0 + warp * 16 + g;
#pragma unroll
    for (int dt = 0; dt < 8; dt++) {
        int col = h * 64 + dt * 8 + 2 * t4;
        *(unsigned*)(O + (size_t)(b * S_ + row) * D_ + col) =
            packh(oacc[dt][0] * il0, oacc[dt][1] * il0);
        *(unsigned*)(O + (size_t)(b * S_ + row + 8) * D_ + col) =
            packh(oacc[dt][2] * il1, oacc[dt][3] * il1);
    }
}

// ---------------- Selector ----------------
__global__ __launch_bounds__(128) void selector_kernel(const float* __restrict__ h,
                                                       const float* __restrict__ Wsel) {
    int t = blockIdx.x * 4 + (threadIdx.x >> 5);
    int lane = threadIdx.x & 31;
    float acc[16];
#pragma unroll
    for (int e = 0; e < 16; e++) acc[e] = 0.f;
    const float* hr = h + (size_t)t * D_;
    for (int d = lane; d < D_; d += 32) {
        float hv = hr[d];
        const float4* w = (const float4*)(Wsel + (size_t)d * E_);
        float4 w0 = w[0], w1 = w[1], w2 = w[2], w3 = w[3];
        acc[0]  = fmaf(hv, w0.x, acc[0]);  acc[1]  = fmaf(hv, w0.y, acc[1]);
        acc[2]  = fmaf(hv, w0.z, acc[2]);  acc[3]  = fmaf(hv, w0.w, acc[3]);
        acc[4]  = fmaf(hv, w1.x, acc[4]);  acc[5]  = fmaf(hv, w1.y, acc[5]);
        acc[6]  = fmaf(hv, w1.z, acc[6]);  acc[7]  = fmaf(hv, w1.w, acc[7]);
        acc[8]  = fmaf(hv, w2.x, acc[8]);  acc[9]  = fmaf(hv, w2.y, acc[9]);
        acc[10] = fmaf(hv, w2.z, acc[10]); acc[11] = fmaf(hv, w2.w, acc[11]);
        acc[12] = fmaf(hv, w3.x, acc[12]); acc[13] = fmaf(hv, w3.y, acc[13]);
        acc[14] = fmaf(hv, w3.z, acc[14]); acc[15] = fmaf(hv, w3.w, acc[15]);
    }
#pragma unroll
    for (int e = 0; e < 16; e++)
#pragma unroll
        for (int o = 16; o; o >>= 1) acc[e] += __shfl_xor_sync(0xffffffffu, acc[e], o);
    if (lane == 0) {
        float v1 = -1.f, v2 = -1.f;
        int i1 = 0, i2 = 0;
#pragma unroll
        for (int e = 0; e < 16; e++) {
            float sg = 1.0f / (1.0f + __expf(-acc[e]));
            if (sg > v1) { v2 = v1; i2 = i1; v1 = sg; i1 = e; }
            else if (sg > v2) { v2 = sg; i2 = e; }
        }
        int p1 = atomicAdd(&g_cnt[i1], 1);
        g_elist[i1 * T_ + p1] = t;
        g_egate[i1 * T_ + p1] = v1;
        int p2 = atomicAdd(&g_cnt[i2], 1);
        g_elist[i2 * T_ + p2] = t;
        g_egate[i2 * T_ + p2] = v2;
    }
}

// ---------------- launch ----------------
extern "C" void kernel_launch(void* const* d_in, const int* in_sizes, int n_in,
                              void* d_out, int out_size) {
    (void)in_sizes; (void)n_in; (void)out_size;
    const float* x    = (const float*)d_in[0];
    const float* Wq   = (const float*)d_in[1];
    const float* Wk   = (const float*)d_in[2];
    const float* Wv   = (const float*)d_in[3];
    const float* Wo   = (const float*)d_in[4];
    const float* ln1s = (const float*)d_in[5];
    const float* ln1b = (const float*)d_in[6];
    const float* ln2s = (const float*)d_in[7];
    const float* ln2b = (const float*)d_in[8];
    const float* Wsel = (const float*)d_in[9];
    const float* W1   = (const float*)d_in[10];
    const float* W2   = (const float*)d_in[11];
    float* out = (float*)d_out;

    __half *wqkvT, *woT, *w1T, *w2T, *h1h, *qkvh, *ctxh, *h2h, *uph;
    float *h2p;
    cudaGetSymbolAddress((void**)&wqkvT, g_wqkvT);
    cudaGetSymbolAddress((void**)&woT,   g_woT);
    cudaGetSymbolAddress((void**)&w1T,   g_w1T);
    cudaGetSymbolAddress((void**)&w2T,   g_w2T);
    cudaGetSymbolAddress((void**)&h1h,   g_h1h);
    cudaGetSymbolAddress((void**)&qkvh,  g_qkvh);
    cudaGetSymbolAddress((void**)&ctxh,  g_ctxh);
    cudaGetSymbolAddress((void**)&h2h,   g_h2h);
    cudaGetSymbolAddress((void**)&uph,   g_uph);
    cudaGetSymbolAddress((void**)&h2p,   g_h2);

    static cudaStream_t s_side = nullptr;
    static cudaEvent_t ev_fork = nullptr, ev_join = nullptr;
    static int attrs_set = 0;
    if (s_side == nullptr) {
        cudaStreamCreateWithFlags(&s_side, cudaStreamNonBlocking);
        cudaEventCreateWithFlags(&ev_fork, cudaEventDisableTiming);
        cudaEventCreateWithFlags(&ev_join, cudaEventDisableTiming);
    }
    if (!attrs_set) {
        cudaFuncSetAttribute(gemm_ld<0>, cudaFuncAttributeMaxDynamicSharedMemorySize, TCSM);
        cudaFuncSetAttribute(gemm_ld<1>, cudaFuncAttributeMaxDynamicSharedMemorySize, TCSM);
        cudaFuncSetAttribute(moe_ld<0>, cudaFuncAttributeMaxDynamicSharedMemorySize, TCSM);
        cudaFuncSetAttribute(moe_ld<1>, cudaFuncAttributeMaxDynamicSharedMemorySize, TCSM);
        cudaFuncSetAttribute(attn_h_kernel, cudaFuncAttributeMaxDynamicSharedMemorySize, ATSM);
        attrs_set = 1;
    }

    // fork: Wo transpose + per-expert MoE weight transposes overlap QKV+attention
    cudaEventRecord(ev_fork, 0);
    cudaStreamWaitEvent(s_side, ev_fork, 0);
    conv_f2h_T<<<dim3(32, 32), 256, 0, s_side>>>(Wo, woT);
    conv_TE<<<dim3(8, 32, E_), 256, 0, s_side>>>(W1, w1T, 1024, 256);
    conv_TE<<<dim3(32, 8, E_), 256, 0, s_side>>>(W2, w2T, 256, 1024);
    cudaEventRecord(ev_join, s_side);

    // main path
    conv_f2h_T3<<<dim3(32, 32, 3), 256>>>(Wq, Wk, Wv, wqkvT);
    zero_cnt_kernel<<<1, 32>>>();
    ln_h_kernel<<<T_, 256>>>(x, ln1s, ln1b, h1h);

    gemm_ld<0><<<dim3(8, 32, 3), 256, TCSM>>>(
        h1h, wqkvT, nullptr, nullptr, qkvh);

    attn_h_kernel<<<dim3(S_ / 128, B_ * H_), 256, ATSM>>>(
        qkvh, qkvh + (size_t)T_ * D_, qkvh + 2 * (size_t)T_ * D_, ctxh);

    cudaStreamWaitEvent(0, ev_join, 0);

    // out = x + ctx @ Wo (single fp32 destination; ln_dual reads it back)
    gemm_ld<1><<<dim3(8, 32, 1), 256, TCSM>>>(
        ctxh, woT, x, out, nullptr);

    ln_dual_kernel<<<T_, 256>>>(out, ln2s, ln2b, h2p, h2h);
    selector_kernel<<<T_ / 4, 128>>>(h2p, Wsel);

    moe_ld<0><<<dim3(F_ / 128, T_ / 128, E_), 256, TCSM>>>(h2h, w1T, uph, nullptr);
    moe_ld<1><<<dim3(D_ / 128, T_ / 128, E_), 256, TCSM>>>(uph, w2T, nullptr, out);
}

// round 16
// speedup vs baseline: 1.0789x; 1.0789x over previous
#include <cuda_runtime.h>
#include <cuda_fp16.h>
#include <stdint.h>
#include <cstdint>
#include <math.h>

#define B_  2
#define S_  2048
#define D_  1024
#define H_  16
#define DH_ 64
#define E_  16
#define F_  256
#define T_  (B_*S_)

// ---------------- scratch ----------------
__device__ __half g_wqkvT[(size_t)3*D_*D_];   // transposed [N][K] per matrix
__device__ __half g_woT[(size_t)D_*D_];
__device__ __half g_w1T[(size_t)E_*F_*D_];    // per-expert [F][D]
__device__ __half g_w2T[(size_t)E_*D_*F_];    // per-expert [D][F]
__device__ __half g_h1h[(size_t)T_*D_];
__device__ __half g_qkvh[(size_t)3*T_*D_];
__device__ __half g_ctxh[(size_t)T_*D_];
__device__ __half g_h2h[(size_t)T_*D_];
__device__ __half g_uph[(size_t)E_*T_*F_];
__device__ float g_h2[(size_t)T_*D_];
__device__ int   g_cnt[E_];
__device__ int   g_elist[E_*T_];
__device__ float g_egate[E_*T_];

__global__ void zero_cnt_kernel() {
    if (threadIdx.x < E_) g_cnt[threadIdx.x] = 0;
}

// ---------------- helpers ----------------
__device__ __forceinline__ unsigned packh(float lo, float hi) {
    unsigned u;
    asm("cvt.rn.f16x2.f32 %0, %1, %2;" : "=r"(u) : "f"(hi), "f"(lo));
    return u;
}

__device__ __forceinline__ void mma16(float* d, const unsigned* a, unsigned b0, unsigned b1) {
    asm volatile(
        "mma.sync.aligned.m16n8k16.row.col.f32.f16.f16.f32 "
        "{%0,%1,%2,%3},{%4,%5,%6,%7},{%8,%9},{%0,%1,%2,%3};"
        : "+f"(d[0]), "+f"(d[1]), "+f"(d[2]), "+f"(d[3])
        : "r"(a[0]), "r"(a[1]), "r"(a[2]), "r"(a[3]), "r"(b0), "r"(b1));
}

__device__ __forceinline__ uint32_t smem_u32(const void* p) {
    uint32_t a;
    asm("{ .reg .u64 t; cvta.to.shared.u64 t, %1; cvt.u32.u64 %0, t; }" : "=r"(a) : "l"(p));
    return a;
}

__device__ __forceinline__ void ldsm4(unsigned* r, uint32_t addr) {
    asm volatile("ldmatrix.sync.aligned.m8n8.x4.shared.b16 {%0,%1,%2,%3}, [%4];"
                 : "=r"(r[0]), "=r"(r[1]), "=r"(r[2]), "=r"(r[3]) : "r"(addr));
}

__device__ __forceinline__ void ldsm4t(unsigned* r, uint32_t addr) {
    asm volatile("ldmatrix.sync.aligned.m8n8.x4.trans.shared.b16 {%0,%1,%2,%3}, [%4];"
                 : "=r"(r[0]), "=r"(r[1]), "=r"(r[2]), "=r"(r[3]) : "r"(addr));
}

#define CP_ASYNC16(dst, src) \
    asm volatile("cp.async.cg.shared.global [%0], [%1], 16;" :: "r"(dst), "l"(src))
#define CP_COMMIT() asm volatile("cp.async.commit_group;")
#define CP_WAIT(n)  asm volatile("cp.async.wait_group %0;" :: "n"(n))

// ---------------- fp32 [1024][1024] -> transposed fp16 [N][K] -------------------
__global__ __launch_bounds__(256) void conv_f2h_T(const float* __restrict__ s,
                                                  __half* __restrict__ d) {
    __shared__ float t[32][33];
    int bx = blockIdx.x * 32;
    int by = blockIdx.y * 32;
    int lx = threadIdx.x & 31, ly = threadIdx.x >> 5;
#pragma unroll
    for (int i = 0; i < 4; i++) {
        int r = ly + i * 8;
        t[r][lx] = s[(size_t)(by + r) * 1024 + bx + lx];
    }
    __syncthreads();
#pragma unroll
    for (int i = 0; i < 4; i++) {
        int r = ly + i * 8;
        d[(size_t)(bx + r) * 1024 + by + lx] = __float2half(t[lx][r]);
    }
}

// ---------------- fused QKV transpose (z selects matrix) -----------------------
__global__ __launch_bounds__(256) void conv_f2h_T3(const float* __restrict__ s0,
                                                   const float* __restrict__ s1,
                                                   const float* __restrict__ s2,
                                                   __half* __restrict__ d) {
    const float* s = (blockIdx.z == 0) ? s0 : ((blockIdx.z == 1) ? s1 : s2);
    __half* dz = d + (size_t)blockIdx.z * 1024 * 1024;
    __shared__ float t[32][33];
    int bx = blockIdx.x * 32;
    int by = blockIdx.y * 32;
    int lx = threadIdx.x & 31, ly = threadIdx.x >> 5;
#pragma unroll
    for (int i = 0; i < 4; i++) {
        int r = ly + i * 8;
        t[r][lx] = s[(size_t)(by + r) * 1024 + bx + lx];
    }
    __syncthreads();
#pragma unroll
    for (int i = 0; i < 4; i++) {
        int r = ly + i * 8;
        dz[(size_t)(bx + r) * 1024 + by + lx] = __float2half(t[lx][r]);
    }
}

// ---------------- per-expert fp32 [R][C] -> fp16 [C][R] ------------------------
__global__ __launch_bounds__(256) void conv_TE(const float* __restrict__ s,
                                               __half* __restrict__ d,
                                               int R, int C) {
    const float* se = s + (size_t)blockIdx.z * R * C;
    __half* de = d + (size_t)blockIdx.z * R * C;
    __shared__ float t[32][33];
    int bx = blockIdx.x * 32;
    int by = blockIdx.y * 32;
    int lx = threadIdx.x & 31, ly = threadIdx.x >> 5;
#pragma unroll
    for (int i = 0; i < 4; i++) {
        int r = ly + i * 8;
        t[r][lx] = se[(size_t)(by + r) * C + bx + lx];
    }
    __syncthreads();
#pragma unroll
    for (int i = 0; i < 4; i++) {
        int r = ly + i * 8;
        de[(size_t)(bx + r) * R + by + lx] = __float2half(t[lx][r]);
    }
}

// ---------------- LayerNorm (fp16 out) ----------------
__global__ __launch_bounds__(256) void ln_h_kernel(const float* __restrict__ x,
                                                   const float* __restrict__ sc,
                                                   const float* __restrict__ bi,
                                                   __half* __restrict__ o) {
    int t = blockIdx.x;
    const float* xr = x + (size_t)t * D_;
    __half* orow = o + (size_t)t * D_;
    float v[4];
    float s = 0.f, s2 = 0.f;
#pragma unroll
    for (int i = 0; i < 4; i++) {
        v[i] = xr[threadIdx.x + i * 256];
        s  += v[i];
        s2 += v[i] * v[i];
    }
#pragma unroll
    for (int off = 16; off; off >>= 1) {
        s  += __shfl_xor_sync(0xffffffffu, s,  off);
        s2 += __shfl_xor_sync(0xffffffffu, s2, off);
    }
    __shared__ float ws[8], ws2[8];
    int w = threadIdx.x >> 5, ln = threadIdx.x & 31;
    if (ln == 0) { ws[w] = s; ws2[w] = s2; }
    __syncthreads();
    float S = 0.f, S2 = 0.f;
#pragma unroll
    for (int i = 0; i < 8; i++) { S += ws[i]; S2 += ws2[i]; }
    float mu  = S * (1.0f / D_);
    float var = S2 * (1.0f / D_) - mu * mu;
    float inv = rsqrtf(var + 1e-5f);
#pragma unroll
    for (int i = 0; i < 4; i++) {
        int d = threadIdx.x + i * 256;
        orow[d] = __float2half((v[i] - mu) * inv * sc[d] + bi[d]);
    }
}

// ---------------- LayerNorm dual output (fp32 + fp16) ----------------
__global__ __launch_bounds__(256) void ln_dual_kernel(const float* __restrict__ x,
                                                      const float* __restrict__ sc,
                                                      const float* __restrict__ bi,
                                                      float* __restrict__ of,
                                                      __half* __restrict__ oh) {
    int t = blockIdx.x;
    const float* xr = x + (size_t)t * D_;
    float v[4];
    float s = 0.f, s2 = 0.f;
#pragma unroll
    for (int i = 0; i < 4; i++) {
        v[i] = xr[threadIdx.x + i * 256];
        s  += v[i];
        s2 += v[i] * v[i];
    }
#pragma unroll
    for (int off = 16; off; off >>= 1) {
        s  += __shfl_xor_sync(0xffffffffu, s,  off);
        s2 += __shfl_xor_sync(0xffffffffu, s2, off);
    }
    __shared__ float ws[8], ws2[8];
    int w = threadIdx.x >> 5, ln = threadIdx.x & 31;
    if (ln == 0) { ws[w] = s; ws2[w] = s2; }
    __syncthreads();
    float S = 0.f, S2 = 0.f;
#pragma unroll
    for (int i = 0; i < 8; i++) { S += ws[i]; S2 += ws2[i]; }
    float mu  = S * (1.0f / D_);
    float var = S2 * (1.0f / D_) - mu * mu;
    float inv = rsqrtf(var + 1e-5f);
#pragma unroll
    for (int i = 0; i < 4; i++) {
        int d = threadIdx.x + i * 256;
        float r = (v[i] - mu) * inv * sc[d] + bi[d];
        of[(size_t)t * D_ + d] = r;
        oh[(size_t)t * D_ + d] = __float2half(r);
    }
}

// ---------------- GEMM: ldmatrix + cp.async 3-stage, occ-2 ----------------------
#define STG_ 36864
#define TCSM (3 * STG_)

template <int MODE>
__global__ __launch_bounds__(256, 2) void gemm_ld(const __half* __restrict__ A,
                                                  const __half* __restrict__ Bt,
                                                  const float* __restrict__ Res,
                                                  float* __restrict__ Cf,
                                                  __half* __restrict__ Cb) {
    extern __shared__ char dsm[];
    uint32_t smb = smem_u32(dsm);

    int tid = threadIdx.x, warp = tid >> 5, lane = tid & 31;
    int g = lane >> 2, t4 = lane & 3;
    int wm = warp >> 1, wn = warp & 1;
    int bx = blockIdx.x * 128, by = blockIdx.y * 128;
    const __half* Bz = Bt + (size_t)blockIdx.z * D_ * D_;

    float acc[2][8][4];
#pragma unroll
    for (int i = 0; i < 2; i++)
#pragma unroll
        for (int j = 0; j < 8; j++)
#pragma unroll
            for (int q = 0; q < 4; q++) acc[i][j][q] = 0.f;

    int lr = tid >> 1;
    int lsh = (tid & 1) * 32;
    int lsb = (tid & 1) * 64;
    const __half* gA = A  + (size_t)(by + lr) * D_ + lsh;
    const __half* gB = Bz + (size_t)(bx + lr) * D_ + lsh;
    uint32_t sA = smb + lr * 144 + lsb;
    uint32_t sB = smb + 18432 + lr * 144 + lsb;

#pragma unroll
    for (int j = 0; j < 4; j++) {
        CP_ASYNC16(sA + j * 16, gA + j * 8);
        CP_ASYNC16(sB + j * 16, gB + j * 8);
    }
    CP_COMMIT();
#pragma unroll
    for (int j = 0; j < 4; j++) {
        CP_ASYNC16(sA + STG_ + j * 16, gA + 64 + j * 8);
        CP_ASYNC16(sB + STG_ + j * 16, gB + 64 + j * 8);
    }
    CP_COMMIT();

    uint32_t a_off = (uint32_t)((wm * 32 + (lane & 15)) * 144 + (lane >> 4) * 16);
    uint32_t b_row = (uint32_t)(wn * 64 + ((lane >> 4) & 1) * 8 + (lane & 7));
    uint32_t b_khb = ((lane >> 3) & 1) * 16;

    for (int i = 0; i < 16; i++) {
        int s = i % 3;
        if (i < 15) { CP_WAIT(1); } else { CP_WAIT(0); }
        __syncthreads();
        if (i + 2 < 16) {
            int s2 = (i + 2) % 3;
            int k0 = (i + 2) * 64;
#pragma unroll
            for (int j = 0; j < 4; j++) {
                CP_ASYNC16(sA + s2 * STG_ + j * 16, gA + k0 + j * 8);
                CP_ASYNC16(sB + s2 * STG_ + j * 16, gB + k0 + j * 8);
            }
            CP_COMMIT();
        }

        uint32_t ab = smb + s * STG_;
        uint32_t bb = ab + 18432;
#pragma unroll
        for (int kc = 0; kc < 4; kc++) {
            unsigned afr0[4], afr1[4];
            ldsm4(afr0, ab + a_off + kc * 32);
            ldsm4(afr1, ab + a_off + 16 * 144 + kc * 32);
#pragma unroll
            for (int p = 0; p < 4; p++) {
                unsigned bfr[4];
                ldsm4(bfr, bb + (b_row + p * 16) * 144 + b_khb + kc * 32);
                mma16(acc[0][2 * p],     afr0, bfr[0], bfr[1]);
                mma16(acc[0][2 * p + 1], afr0, bfr[2], bfr[3]);
                mma16(acc[1][2 * p],     afr1, bfr[0], bfr[1]);
                mma16(acc[1][2 * p + 1], afr1, bfr[2], bfr[3]);
            }
        }
    }

    if (MODE == 0) {
        __half* Cz = Cb + (size_t)blockIdx.z * T_ * D_;
#pragma unroll
        for (int mt = 0; mt < 2; mt++) {
#pragma unroll
            for (int nt = 0; nt < 8; nt++) {
                int col = bx + wn * 64 + nt * 8 + 2 * t4;
                size_t r0 = (size_t)(by + wm * 32 + mt * 16 + g);
                *(unsigned*)(Cz + r0 * D_ + col)       = packh(acc[mt][nt][0], acc[mt][nt][1]);
                *(unsigned*)(Cz + (r0 + 8) * D_ + col) = packh(acc[mt][nt][2], acc[mt][nt][3]);
            }
        }
    } else {
#pragma unroll
        for (int mt = 0; mt < 2; mt++) {
#pragma unroll
            for (int nt = 0; nt < 8; nt++) {
                int col = bx + wn * 64 + nt * 8 + 2 * t4;
                size_t r0 = (size_t)(by + wm * 32 + mt * 16 + g);
                size_t r1 = r0 + 8;
                float2 v01 = {acc[mt][nt][0], acc[mt][nt][1]};
                float2 v23 = {acc[mt][nt][2], acc[mt][nt][3]};
                float2 q0 = *(const float2*)(Res + r0 * D_ + col);
                float2 q1 = *(const float2*)(Res + r1 * D_ + col);
                v01.x += q0.x; v01.y += q0.y;
                v23.x += q1.x; v23.y += q1.y;
                *(float2*)(Cf + r0 * D_ + col) = v01;
                *(float2*)(Cf + r1 * D_ + col) = v23;
            }
        }
    }
}

// ---------------- MoE GEMM: ldmatrix + cp.async, gather/scatter, occ-2 ----------
template <int MODE>
__global__ __launch_bounds__(256, 2) void moe_ld(const __half* __restrict__ Ab,
                                                 const __half* __restrict__ Wt,
                                                 __half* __restrict__ Uph,
                                                 float* __restrict__ out) {
    const int Nn = (MODE == 0) ? F_ : D_;
    const int Kk = (MODE == 0) ? D_ : F_;
    const int NT = Kk / 64;
    int e = blockIdx.z;
    int n = g_cnt[e];
    int rb = blockIdx.y * 128;
    if (rb >= n) return;

    extern __shared__ char dsm[];
    uint32_t smb = smem_u32(dsm);

    int tid = threadIdx.x, warp = tid >> 5, lane = tid & 31;
    int g = lane >> 2, t4 = lane & 3;
    int wm = warp >> 1, wn = warp & 1;
    int bx = blockIdx.x * 128;
    const __half* Wz = Wt + (size_t)e * Kk * Nn;

    float acc[2][8][4];
#pragma unroll
    for (int i = 0; i < 2; i++)
#pragma unroll
        for (int j = 0; j < 8; j++)
#pragma unroll
            for (int q = 0; q < 4; q++) acc[i][j][q] = 0.f;

    int lr = tid >> 1;
    int lsh = (tid & 1) * 32;
    int lsb = (tid & 1) * 64;
    const __half* gA;
    if (MODE == 0) {
        int rg = rb + lr;
        int row = (rg < n) ? g_elist[e * T_ + rg] : 0;
        gA = Ab + (size_t)row * D_ + lsh;
    } else {
        gA = Ab + ((size_t)e * T_ + rb + lr) * F_ + lsh;
    }
    const __half* gB = Wz + (size_t)(bx + lr) * Kk + lsh;
    uint32_t sA = smb + lr * 144 + lsb;
    uint32_t sB = smb + 18432 + lr * 144 + lsb;

#pragma unroll
    for (int j = 0; j < 4; j++) {
        CP_ASYNC16(sA + j * 16, gA + j * 8);
        CP_ASYNC16(sB + j * 16, gB + j * 8);
    }
    CP_COMMIT();
#pragma unroll
    for (int j = 0; j < 4; j++) {
        CP_ASYNC16(sA + STG_ + j * 16, gA + 64 + j * 8);
        CP_ASYNC16(sB + STG_ + j * 16, gB + 64 + j * 8);
    }
    CP_COMMIT();

    uint32_t a_off = (uint32_t)((wm * 32 + (lane & 15)) * 144 + (lane >> 4) * 16);
    uint32_t b_row = (uint32_t)(wn * 64 + ((lane >> 4) & 1) * 8 + (lane & 7));
    uint32_t b_khb = ((lane >> 3) & 1) * 16;

    for (int i = 0; i < NT; i++) {
        int s = i % 3;
        if (i < NT - 1) { CP_WAIT(1); } else { CP_WAIT(0); }
        __syncthreads();
        if (i + 2 < NT) {
            int s2 = (i + 2) % 3;
            int k0 = (i + 2) * 64;
#pragma unroll
            for (int j = 0; j < 4; j++) {
                CP_ASYNC16(sA + s2 * STG_ + j * 16, gA + k0 + j * 8);
                CP_ASYNC16(sB + s2 * STG_ + j * 16, gB + k0 + j * 8);
            }
            CP_COMMIT();
        }

        uint32_t ab = smb + s * STG_;
        uint32_t bb = ab + 18432;
#pragma unroll
        for (int kc = 0; kc < 4; kc++) {
            unsigned afr0[4], afr1[4];
            ldsm4(afr0, ab + a_off + kc * 32);
            ldsm4(afr1, ab + a_off + 16 * 144 + kc * 32);
#pragma unroll
            for (int p = 0; p < 4; p++) {
                unsigned bfr[4];
                ldsm4(bfr, bb + (b_row + p * 16) * 144 + b_khb + kc * 32);
                mma16(acc[0][2 * p],     afr0, bfr[0], bfr[1]);
                mma16(acc[0][2 * p + 1], afr0, bfr[2], bfr[3]);
                mma16(acc[1][2 * p],     afr1, bfr[0], bfr[1]);
                mma16(acc[1][2 * p + 1], afr1, bfr[2], bfr[3]);
            }
        }
    }

    if (MODE == 0) {
#pragma unroll
        for (int mt = 0; mt < 2; mt++) {
            int rg0 = rb + wm * 32 + mt * 16 + g;
            int rg1 = rg0 + 8;
            float gt0 = (rg0 < n) ? g_egate[e * T_ + rg0] : 0.f;
            float gt1 = (rg1 < n) ? g_egate[e * T_ + rg1] : 0.f;
#pragma unroll
            for (int nt = 0; nt < 8; nt++) {
                int col = bx + wn * 64 + nt * 8 + 2 * t4;
                if (rg0 < n)
                    *(unsigned*)(Uph + ((size_t)e * T_ + rg0) * F_ + col) =
                        packh(fmaxf(acc[mt][nt][0], 0.f) * gt0,
                              fmaxf(acc[mt][nt][1], 0.f) * gt0);
                if (rg1 < n)
                    *(unsigned*)(Uph + ((size_t)e * T_ + rg1) * F_ + col) =
                        packh(fmaxf(acc[mt][nt][2], 0.f) * gt1,
                              fmaxf(acc[mt][nt][3], 0.f) * gt1);
            }
        }
    } else {
#pragma unroll
        for (int mt = 0; mt < 2; mt++) {
            int rg0 = rb + wm * 32 + mt * 16 + g;
            int rg1 = rg0 + 8;
            int t0 = (rg0 < n) ? g_elist[e * T_ + rg0] : -1;
            int t1 = (rg1 < n) ? g_elist[e * T_ + rg1] : -1;
#pragma unroll
            for (int nt = 0; nt < 8; nt++) {
                int col = bx + wn * 64 + nt * 8 + 2 * t4;
                if (t0 >= 0) {
                    atomicAdd(out + (size_t)t0 * D_ + col,     acc[mt][nt][0]);
                    atomicAdd(out + (size_t)t0 * D_ + col + 1, acc[mt][nt][1]);
                }
                if (t1 >= 0) {
                    atomicAdd(out + (size_t)t1 * D_ + col,     acc[mt][nt][2]);
                    atomicAdd(out + (size_t)t1 * D_ + col + 1, acc[mt][nt][3]);
                }
            }
        }
    }
}

// ---------------- fp16 flash attention: 128-q tile, double-buffered KV (R14) ----
__global__ __launch_bounds__(256) void attn_h_kernel(const __half* __restrict__ Q,
                                                     const __half* __restrict__ Kb,
                                                     const __half* __restrict__ Vb,
                                                     __half* __restrict__ O) {
    __shared__ unsigned KVs[2 * 128 * 36];

    int bh = blockIdx.y;
    int b = bh >> 4, h = bh & 15;
    int q0 = blockIdx.x * 128;
    int tid = threadIdx.x, warp = tid >> 5, lane = tid & 31;
    int g = lane >> 2, t4 = lane & 3;

    uint32_t ksb = smem_u32(KVs);

    // ---- stage Q tile (128 rows) into buffer 0, read fragments ----
#pragma unroll
    for (int i = 0; i < 4; i++) {
        int idx = tid + i * 256;
        int row = idx >> 3, uq = idx & 7;
        *(uint4*)&KVs[row * 36 + uq * 4] =
            *(const uint4*)(Q + (size_t)(b * S_ + q0 + row) * D_ + h * 64 + uq * 8);
    }
    __syncthreads();
    unsigned qf[4][4];
    {
        uint32_t qa = ksb + (warp * 16 + (lane & 15)) * 144 + (lane >> 4) * 16;
#pragma unroll
        for (int kc = 0; kc < 4; kc++) ldsm4(qf[kc], qa + kc * 32);
    }
    __syncthreads();   // qf reads complete before buffer 0 is overwritten

    // ---- prefetch K/V tile 0 into registers ----
    uint4 kp[2], vp[2];
#pragma unroll
    for (int i = 0; i < 2; i++) {
        int idx = tid + i * 256;
        int row = idx >> 3, uq = idx & 7;
        size_t base = (size_t)(b * S_ + row) * D_ + h * 64 + uq * 8;
        kp[i] = *(const uint4*)(Kb + base);
        vp[i] = *(const uint4*)(Vb + base);
    }

    float oacc[8][4];
#pragma unroll
    for (int i = 0; i < 8; i++)
#pragma unroll
        for (int j = 0; j < 4; j++) oacc[i][j] = 0.f;
    float m0 = -1e30f, m1 = -1e30f, l0 = 0.f, l1 = 0.f;

    uint32_t k_row = ((lane >> 4) & 1) * 8 + (lane & 7);
    uint32_t k_khb = ((lane >> 3) & 1) * 16;
    uint32_t v_tok = ((lane >> 3) & 1) * 8 + (lane & 7);
    uint32_t v_dcb = ((lane >> 4) & 1) * 16;

    for (int kt = 0; kt < S_; kt += 64) {
        int buf = (kt >> 6) & 1;
#pragma unroll
        for (int i = 0; i < 2; i++) {
            int idx = tid + i * 256;
            int row = idx >> 3, uq = idx & 7;
            *(uint4*)&KVs[buf * 4608 + row * 36 + uq * 4]        = kp[i];
            *(uint4*)&KVs[buf * 4608 + (64 + row) * 36 + uq * 4] = vp[i];
        }
        __syncthreads();

        {
            int ktn = (kt + 64 < S_) ? kt + 64 : kt;
#pragma unroll
            for (int i = 0; i < 2; i++) {
                int idx = tid + i * 256;
                int row = idx >> 3, uq = idx & 7;
                size_t base = (size_t)(b * S_ + ktn + row) * D_ + h * 64 + uq * 8;
                kp[i] = *(const uint4*)(Kb + base);
                vp[i] = *(const uint4*)(Vb + base);
            }
        }

        uint32_t kbase = ksb + buf * 18432;
        uint32_t vbase = kbase + 64 * 144;

        float sacc[8][4];
#pragma unroll
        for (int i = 0; i < 8; i++)
#pragma unroll
            for (int j = 0; j < 4; j++) sacc[i][j] = 0.f;
#pragma unroll
        for (int kc = 0; kc < 4; kc++) {
#pragma unroll
            for (int p = 0; p < 4; p++) {
                unsigned kb[4];
                ldsm4(kb, kbase + (k_row + p * 16) * 144 + k_khb + kc * 32);
                mma16(sacc[2 * p],     qf[kc], kb[0], kb[1]);
                mma16(sacc[2 * p + 1], qf[kc], kb[2], kb[3]);
            }
        }
#pragma unroll
        for (int nt = 0; nt < 8; nt++)
#pragma unroll
            for (int j = 0; j < 4; j++) sacc[nt][j] *= 0.125f;

        float mx0 = -1e30f, mx1 = -1e30f;
#pragma unroll
        for (int nt = 0; nt < 8; nt++) {
            mx0 = fmaxf(mx0, fmaxf(sacc[nt][0], sacc[nt][1]));
            mx1 = fmaxf(mx1, fmaxf(sacc[nt][2], sacc[nt][3]));
        }
        mx0 = fmaxf(mx0, __shfl_xor_sync(0xffffffffu, mx0, 1));
        mx0 = fmaxf(mx0, __shfl_xor_sync(0xffffffffu, mx0, 2));
        mx1 = fmaxf(mx1, __shfl_xor_sync(0xffffffffu, mx1, 1));
        mx1 = fmaxf(mx1, __shfl_xor_sync(0xffffffffu, mx1, 2));
        float mn0 = fmaxf(m0, mx0), mn1 = fmaxf(m1, mx1);
        float al0 = __expf(m0 - mn0), al1 = __expf(m1 - mn1);
        float rs0 = 0.f, rs1 = 0.f;
#pragma unroll
        for (int nt = 0; nt < 8; nt++) {
            sacc[nt][0] = __expf(sacc[nt][0] - mn0);
            sacc[nt][1] = __expf(sacc[nt][1] - mn0);
            sacc[nt][2] = __expf(sacc[nt][2] - mn1);
            sacc[nt][3] = __expf(sacc[nt][3] - mn1);
            rs0 += sacc[nt][0] + sacc[nt][1];
            rs1 += sacc[nt][2] + sacc[nt][3];
        }
        rs0 += __shfl_xor_sync(0xffffffffu, rs0, 1);
        rs0 += __shfl_xor_sync(0xffffffffu, rs0, 2);
        rs1 += __shfl_xor_sync(0xffffffffu, rs1, 1);
        rs1 += __shfl_xor_sync(0xffffffffu, rs1, 2);
        l0 = l0 * al0 + rs0;
        l1 = l1 * al1 + rs1;
        m0 = mn0; m1 = mn1;
#pragma unroll
        for (int dt = 0; dt < 8; dt++) {
            oacc[dt][0] *= al0; oacc[dt][1] *= al0;
            oacc[dt][2] *= al1; oacc[dt][3] *= al1;
        }

#pragma unroll
        for (int kc = 0; kc < 4; kc++) {
            unsigned pf[4];
            pf[0] = packh(sacc[2 * kc][0],     sacc[2 * kc][1]);
            pf[1] = packh(sacc[2 * kc][2],     sacc[2 * kc][3]);
            pf[2] = packh(sacc[2 * kc + 1][0], sacc[2 * kc + 1][1]);
            pf[3] = packh(sacc[2 * kc + 1][2], sacc[2 * kc + 1][3]);
#pragma unroll
            for (int p = 0; p < 4; p++) {
                unsigned vb[4];
                ldsm4t(vb, vbase + (v_tok + kc * 16) * 144 + v_dcb + p * 32);
                mma16(oacc[2 * p],     pf, vb[0], vb[1]);
                mma16(oacc[2 * p + 1], pf, vb[2], vb[3]);
            }
        }
    }

    float il0 = 1.0f / l0, il1 = 1.0f / l1;
    int row = q0 + warp * 16 + g;
#pragma unroll
    for (int dt = 0; dt < 8; dt++) {
        int col = h * 64 + dt * 8 + 2 * t4;
        *(unsigned*)(O + (size_t)(b * S_ + row) * D_ + col) =
            packh(oacc[dt][0] * il0, oacc[dt][1] * il0);
        *(unsigned*)(O + (size_t)(b * S_ + row + 8) * D_ + col) =
            packh(oacc[dt][2] * il1, oacc[dt][3] * il1);
    }
}

// ---------------- Selector ----------------
__global__ __launch_bounds__(128) void selector_kernel(const float* __restrict__ h,
                                                       const float* __restrict__ Wsel) {
    int t = blockIdx.x * 4 + (threadIdx.x >> 5);
    int lane = threadIdx.x & 31;
    float acc[16];
#pragma unroll
    for (int e = 0; e < 16; e++) acc[e] = 0.f;
    const float* hr = h + (size_t)t * D_;
    for (int d = lane; d < D_; d += 32) {
        float hv = hr[d];
        const float4* w = (const float4*)(Wsel + (size_t)d * E_);
        float4 w0 = w[0], w1 = w[1], w2 = w[2], w3 = w[3];
        acc[0]  = fmaf(hv, w0.x, acc[0]);  acc[1]  = fmaf(hv, w0.y, acc[1]);
        acc[2]  = fmaf(hv, w0.z, acc[2]);  acc[3]  = fmaf(hv, w0.w, acc[3]);
        acc[4]  = fmaf(hv, w1.x, acc[4]);  acc[5]  = fmaf(hv, w1.y, acc[5]);
        acc[6]  = fmaf(hv, w1.z, acc[6]);  acc[7]  = fmaf(hv, w1.w, acc[7]);
        acc[8]  = fmaf(hv, w2.x, acc[8]);  acc[9]  = fmaf(hv, w2.y, acc[9]);
        acc[10] = fmaf(hv, w2.z, acc[10]); acc[11] = fmaf(hv, w2.w, acc[11]);
        acc[12] = fmaf(hv, w3.x, acc[12]); acc[13] = fmaf(hv, w3.y, acc[13]);
        acc[14] = fmaf(hv, w3.z, acc[14]); acc[15] = fmaf(hv, w3.w, acc[15]);
    }
#pragma unroll
    for (int e = 0; e < 16; e++)
#pragma unroll
        for (int o = 16; o; o >>= 1) acc[e] += __shfl_xor_sync(0xffffffffu, acc[e], o);
    if (lane == 0) {
        float v1 = -1.f, v2 = -1.f;
        int i1 = 0, i2 = 0;
#pragma unroll
        for (int e = 0; e < 16; e++) {
            float sg = 1.0f / (1.0f + __expf(-acc[e]));
            if (sg > v1) { v2 = v1; i2 = i1; v1 = sg; i1 = e; }
            else if (sg > v2) { v2 = sg; i2 = e; }
        }
        int p1 = atomicAdd(&g_cnt[i1], 1);
        g_elist[i1 * T_ + p1] = t;
        g_egate[i1 * T_ + p1] = v1;
        int p2 = atomicAdd(&g_cnt[i2], 1);
        g_elist[i2 * T_ + p2] = t;
        g_egate[i2 * T_ + p2] = v2;
    }
}

// ---------------- launch ----------------
extern "C" void kernel_launch(void* const* d_in, const int* in_sizes, int n_in,
                              void* d_out, int out_size) {
    (void)in_sizes; (void)n_in; (void)out_size;
    const float* x    = (const float*)d_in[0];
    const float* Wq   = (const float*)d_in[1];
    const float* Wk   = (const float*)d_in[2];
    const float* Wv   = (const float*)d_in[3];
    const float* Wo   = (const float*)d_in[4];
    const float* ln1s = (const float*)d_in[5];
    const float* ln1b = (const float*)d_in[6];
    const float* ln2s = (const float*)d_in[7];
    const float* ln2b = (const float*)d_in[8];
    const float* Wsel = (const float*)d_in[9];
    const float* W1   = (const float*)d_in[10];
    const float* W2   = (const float*)d_in[11];
    float* out = (float*)d_out;

    __half *wqkvT, *woT, *w1T, *w2T, *h1h, *qkvh, *ctxh, *h2h, *uph;
    float *h2p;
    cudaGetSymbolAddress((void**)&wqkvT, g_wqkvT);
    cudaGetSymbolAddress((void**)&woT,   g_woT);
    cudaGetSymbolAddress((void**)&w1T,   g_w1T);
    cudaGetSymbolAddress((void**)&w2T,   g_w2T);
    cudaGetSymbolAddress((void**)&h1h,   g_h1h);
    cudaGetSymbolAddress((void**)&qkvh,  g_qkvh);
    cudaGetSymbolAddress((void**)&ctxh,  g_ctxh);
    cudaGetSymbolAddress((void**)&h2h,   g_h2h);
    cudaGetSymbolAddress((void**)&uph,   g_uph);
    cudaGetSymbolAddress((void**)&h2p,   g_h2);

    static cudaStream_t s_side = nullptr;
    static cudaEvent_t ev_fork = nullptr, ev_qkv = nullptr, ev_join = nullptr;
    static int attrs_set = 0;
    if (s_side == nullptr) {
        cudaStreamCreateWithFlags(&s_side, cudaStreamNonBlocking);
        cudaEventCreateWithFlags(&ev_fork, cudaEventDisableTiming);
        cudaEventCreateWithFlags(&ev_qkv,  cudaEventDisableTiming);
        cudaEventCreateWithFlags(&ev_join, cudaEventDisableTiming);
    }
    if (!attrs_set) {
        cudaFuncSetAttribute(gemm_ld<0>, cudaFuncAttributeMaxDynamicSharedMemorySize, TCSM);
        cudaFuncSetAttribute(gemm_ld<1>, cudaFuncAttributeMaxDynamicSharedMemorySize, TCSM);
        cudaFuncSetAttribute(moe_ld<0>, cudaFuncAttributeMaxDynamicSharedMemorySize, TCSM);
        cudaFuncSetAttribute(moe_ld<1>, cudaFuncAttributeMaxDynamicSharedMemorySize, TCSM);
        attrs_set = 1;
    }

    // fork: ALL weight transposes run on the side stream; QKV transpose first
    // (joined before the QKV GEMM), Wo/W1/W2 joined before the Wo GEMM.
    cudaEventRecord(ev_fork, 0);
    cudaStreamWaitEvent(s_side, ev_fork, 0);
    conv_f2h_T3<<<dim3(32, 32, 3), 256, 0, s_side>>>(Wq, Wk, Wv, wqkvT);
    cudaEventRecord(ev_qkv, s_side);
    conv_f2h_T<<<dim3(32, 32), 256, 0, s_side>>>(Wo, woT);
    conv_TE<<<dim3(8, 32, E_), 256, 0, s_side>>>(W1, w1T, 1024, 256);
    conv_TE<<<dim3(32, 8, E_), 256, 0, s_side>>>(W2, w2T, 256, 1024);
    cudaEventRecord(ev_join, s_side);

    // main path overlaps the QKV weight transpose
    zero_cnt_kernel<<<1, 32>>>();
    ln_h_kernel<<<T_, 256>>>(x, ln1s, ln1b, h1h);
    cudaStreamWaitEvent(0, ev_qkv, 0);

    gemm_ld<0><<<dim3(8, 32, 3), 256, TCSM>>>(
        h1h, wqkvT, nullptr, nullptr, qkvh);

    attn_h_kernel<<<dim3(S_ / 128, B_ * H_), 256>>>(
        qkvh, qkvh + (size_t)T_ * D_, qkvh + 2 * (size_t)T_ * D_, ctxh);

    cudaStreamWaitEvent(0, ev_join, 0);

    // out = x + ctx @ Wo (single fp32 destination; ln_dual reads it back)
    gemm_ld<1><<<dim3(8, 32, 1), 256, TCSM>>>(
        ctxh, woT, x, out, nullptr);

    ln_dual_kernel<<<T_, 256>>>(out, ln2s, ln2b, h2p, h2h);
    selector_kernel<<<T_ / 4, 128>>>(h2p, Wsel);

    moe_ld<0><<<dim3(F_ / 128, T_ / 128, E_), 256, TCSM>>>(h2h, w1T, uph, nullptr);
    moe_ld<1><<<dim3(D_ / 128, T_ / 128, E_), 256, TCSM>>>(uph, w2T, nullptr, out);
}